// round 4
// baseline (speedup 1.0000x reference)
#include <cuda_runtime.h>
#include <cuda_bf16.h>
#include <mma.h>
#include <cstdint>

using namespace nvcuda;

#define NUM 16
#define DIM 128
#define NN (NUM*DIM)            // 2048
#define BATCH 4096
#define INC 512
#define OUTC 512
#define STEPS 10
#define KE 6144                 // 3 segments of 2048 (step chain)
#define KEF 1536                // 3 segments of 512  (final GEMM)
#define KSPLIT 8
#define KC 768                  // per-CTA K for step (KE/KSPLIT)

// ---------------- device scratch ----------------
__device__ __align__(16) __nv_bfloat16 g_Text[NN*KE];        // [Thi|Thi|Tlo], 25MB
__device__ __align__(16) __nv_bfloat16 g_Rt[2][DIM*KE];      // [Rhi|Rlo|Rhi] transposed
__device__ __align__(16) float g_P[KSPLIT*NN*DIM];           // split-K partials, 8MB
__device__ __align__(16) float g_S[NN*DIM];                  // sum R_0..R_9
__device__ __align__(16) float g_Rf[NN*DIM];                 // latest R (fp32)
__device__ __align__(16) __nv_bfloat16 g_Iext[BATCH*KEF];    // [Ihi|Ihi|Ilo], 12.6MB
__device__ __align__(16) __nv_bfloat16 g_Gext[OUTC*KEF];     // rows q: [Ghi|Glo|Ghi] over p
__device__ __align__(16) float g_beta[NN];
__device__ __align__(16) float g_h[DIM];
__device__ __align__(16) float g_WpostT[DIM*OUTC];
__device__ __align__(16) float g_T1[DIM*OUTC];
__device__ __align__(16) float g_G[INC*OUTC];
__device__ __align__(16) float g_dvec[OUTC];

// ---------------- step MMA: partial[ks] = T_ext[mtile, ksK] @ Rt[:, ksK]^T ----------------
// 128x128 tile, K=768, wmma bf16 m16n16k16, 8 warps (4x2), fp32 accumulate.
__global__ void __launch_bounds__(256, 1) k_mma_step(int cur) {
    __shared__ __nv_bfloat16 As[128][72];
    __shared__ __nv_bfloat16 Bs[128][72];
    const int ks = blockIdx.x, mt = blockIdx.y;
    const int tid = threadIdx.x, wid = tid >> 5;
    const int wm = wid & 3, wn = wid >> 2;            // warp tile: rows wm*32, cols wn*64
    const __nv_bfloat16* __restrict__ Ag = g_Text + (size_t)mt*128*KE + ks*KC;
    const __nv_bfloat16* __restrict__ Bg = g_Rt[cur] + ks*KC;

    wmma::fragment<wmma::accumulator, 16, 16, 16, float> acc[2][4];
#pragma unroll
    for (int r = 0; r < 2; r++)
#pragma unroll
        for (int c = 0; c < 4; c++) wmma::fill_fragment(acc[r][c], 0.0f);

    const int lrow = tid >> 3, lc8 = (tid & 7) * 8;
    uint4 ra[4], rb[4];
#pragma unroll
    for (int it = 0; it < 4; it++) {
        int row = lrow + it*32;
        ra[it] = *(const uint4*)(Ag + (size_t)row*KE + lc8);
        rb[it] = *(const uint4*)(Bg + (size_t)row*KE + lc8);
    }

    for (int kc = 0; kc < KC/64; kc++) {
#pragma unroll
        for (int it = 0; it < 4; it++) {
            int row = lrow + it*32;
            *(uint4*)&As[row][lc8] = ra[it];
            *(uint4*)&Bs[row][lc8] = rb[it];
        }
        __syncthreads();
        if (kc < KC/64 - 1) {
            const int kb = (kc + 1) * 64;
#pragma unroll
            for (int it = 0; it < 4; it++) {
                int row = lrow + it*32;
                ra[it] = *(const uint4*)(Ag + (size_t)row*KE + kb + lc8);
                rb[it] = *(const uint4*)(Bg + (size_t)row*KE + kb + lc8);
            }
        }
#pragma unroll
        for (int k16 = 0; k16 < 4; k16++) {
            wmma::fragment<wmma::matrix_a, 16, 16, 16, __nv_bfloat16, wmma::row_major> af[2];
            wmma::fragment<wmma::matrix_b, 16, 16, 16, __nv_bfloat16, wmma::col_major> bf[4];
#pragma unroll
            for (int r = 0; r < 2; r++)
                wmma::load_matrix_sync(af[r], &As[wm*32 + r*16][k16*16], 72);
#pragma unroll
            for (int c = 0; c < 4; c++)
                wmma::load_matrix_sync(bf[c], &Bs[wn*64 + c*16][k16*16], 72);
#pragma unroll
            for (int r = 0; r < 2; r++)
#pragma unroll
                for (int c = 0; c < 4; c++)
                    wmma::mma_sync(acc[r][c], af[r], bf[c], acc[r][c]);
        }
        __syncthreads();
    }
    float* P = g_P + ((size_t)ks*NN + mt*128)*DIM;
#pragma unroll
    for (int r = 0; r < 2; r++)
#pragma unroll
        for (int c = 0; c < 4; c++)
            wmma::store_matrix_sync(P + (size_t)(wm*32 + r*16)*DIM + wn*64 + c*16,
                                    acc[r][c], DIM, wmma::mem_row_major);
}

// ---------------- final MMA: out = I_ext @ G_ext^T (bias added separately) ----------------
__global__ void __launch_bounds__(256, 1) k_mma_fin(float* __restrict__ out) {
    __shared__ __nv_bfloat16 As[128][72];
    __shared__ __nv_bfloat16 Bs[128][72];
    const int qt = blockIdx.x, bt = blockIdx.y;
    const int tid = threadIdx.x, wid = tid >> 5;
    const int wm = wid & 3, wn = wid >> 2;
    const __nv_bfloat16* __restrict__ Ag = g_Iext + (size_t)bt*128*KEF;
    const __nv_bfloat16* __restrict__ Bg = g_Gext + (size_t)qt*128*KEF;

    wmma::fragment<wmma::accumulator, 16, 16, 16, float> acc[2][4];
#pragma unroll
    for (int r = 0; r < 2; r++)
#pragma unroll
        for (int c = 0; c < 4; c++) wmma::fill_fragment(acc[r][c], 0.0f);

    const int lrow = tid >> 3, lc8 = (tid & 7) * 8;
    uint4 ra[4], rb[4];
#pragma unroll
    for (int it = 0; it < 4; it++) {
        int row = lrow + it*32;
        ra[it] = *(const uint4*)(Ag + (size_t)row*KEF + lc8);
        rb[it] = *(const uint4*)(Bg + (size_t)row*KEF + lc8);
    }

    for (int kc = 0; kc < KEF/64; kc++) {
#pragma unroll
        for (int it = 0; it < 4; it++) {
            int row = lrow + it*32;
            *(uint4*)&As[row][lc8] = ra[it];
            *(uint4*)&Bs[row][lc8] = rb[it];
        }
        __syncthreads();
        if (kc < KEF/64 - 1) {
            const int kb = (kc + 1) * 64;
#pragma unroll
            for (int it = 0; it < 4; it++) {
                int row = lrow + it*32;
                ra[it] = *(const uint4*)(Ag + (size_t)row*KEF + kb + lc8);
                rb[it] = *(const uint4*)(Bg + (size_t)row*KEF + kb + lc8);
            }
        }
#pragma unroll
        for (int k16 = 0; k16 < 4; k16++) {
            wmma::fragment<wmma::matrix_a, 16, 16, 16, __nv_bfloat16, wmma::row_major> af[2];
            wmma::fragment<wmma::matrix_b, 16, 16, 16, __nv_bfloat16, wmma::col_major> bf[4];
#pragma unroll
            for (int r = 0; r < 2; r++)
                wmma::load_matrix_sync(af[r], &As[wm*32 + r*16][k16*16], 72);
#pragma unroll
            for (int c = 0; c < 4; c++)
                wmma::load_matrix_sync(bf[c], &Bs[wn*64 + c*16][k16*16], 72);
#pragma unroll
            for (int r = 0; r < 2; r++)
#pragma unroll
                for (int c = 0; c < 4; c++)
                    wmma::mma_sync(acc[r][c], af[r], bf[c], acc[r][c]);
        }
        __syncthreads();
    }
    float* op = out + (size_t)bt*128*OUTC + qt*128;
#pragma unroll
    for (int r = 0; r < 2; r++)
#pragma unroll
        for (int c = 0; c < 4; c++)
            wmma::store_matrix_sync(op + (size_t)(wm*32 + r*16)*OUTC + wn*64 + c*16,
                                    acc[r][c], OUTC, wmma::mem_row_major);
}

// out[b][q] += dvec[q]
__global__ void k_bias(float* __restrict__ out) {
    int idx = blockIdx.x*256 + threadIdx.x;
    int q4 = idx & (OUTC/4 - 1);
    float4 v = *(float4*)&out[idx*4];
    float4 d = *(const float4*)&g_dvec[q4*4];
    v.x += d.x; v.y += d.y; v.z += d.z; v.w += d.w;
    *(float4*)&out[idx*4] = v;
}

// ---------------- prep kernels ----------------

__global__ void k_prep(const float* __restrict__ life, const float* __restrict__ bl) {
    int j = blockIdx.x, g = threadIdx.x;
    float s = 0.f;
#pragma unroll
    for (int i = 0; i < NUM; i++) {
        float gt = fmaxf(life[i*NUM + j], 0.f);
        s += gt * bl[(i*NUM + j)*DIM + g];
    }
    g_beta[j*DIM + g] = s;
}

__global__ void k_transpose(const float* __restrict__ Wpost) {
    int e = blockIdx.x, q = threadIdx.x;
    g_WpostT[e*OUTC + q] = Wpost[q*DIM + e];
}

// T_ext[(i,f)][(j,g)] split of gate[i,j]*W[i,j,g,f]; segments [Thi|Thi|Tlo]
__global__ void k_make_T(const float* __restrict__ W, const float* __restrict__ life) {
    const int j = blockIdx.x, i = blockIdx.y;
    const float gate = fmaxf(life[i*NUM + j], 0.f);
    const float* __restrict__ Wb = W + (size_t)(i*NUM + j)*DIM*DIM;
    __shared__ float sm[32][DIM + 1];
    const int tid = threadIdx.x;
    for (int g0 = 0; g0 < DIM; g0 += 32) {
        for (int u = tid; u < 32*DIM; u += 256) {
            int gg = u >> 7, f = u & 127;
            sm[gg][f] = Wb[(size_t)(g0 + gg)*DIM + f];
        }
        __syncthreads();
        int f = tid >> 1, hh = tid & 1;
        size_t row = (size_t)(i*DIM + f)*KE;
#pragma unroll
        for (int k = 0; k < 16; k++) {
            int gg = hh*16 + k;
            float x = gate * sm[gg][f];
            __nv_bfloat16 h = __float2bfloat16(x);
            __nv_bfloat16 l = __float2bfloat16(x - __bfloat162float(h));
            int col = j*DIM + g0 + gg;
            g_Text[row + col]        = h;
            g_Text[row + 2048 + col] = h;
            g_Text[row + 4096 + col] = l;
        }
        __syncthreads();
    }
}

// Rt[0] = transposed split of R_0 (identity columns of block 15): [Rhi|Rlo|Rhi]
__global__ void k_init0() {
    int e = blockIdx.x;
    for (int c = threadIdx.x; c < KE; c += 256) {
        int seg = c >> 11, cc = c & 2047;
        float v = ((seg == 0 || seg == 2) && cc == (NN - DIM) + e) ? 1.f : 0.f;
        g_Rt[0][(size_t)e*KE + c] = __float2bfloat16(v);
    }
}
__global__ void k_initS() {
    int r = blockIdx.x, e = threadIdx.x;
    g_S[r*DIM + e] = (r == (NN - DIM) + e) ? 1.f : 0.f;
}

// reduce split-K partials -> Rf (fp32), S accum, re-split transposed into Rt[cur^1]
__global__ void k_reduce2(int cur, int addS) {
    const int mt = blockIdx.x, sl = blockIdx.y;
    const int base_r = mt*128 + sl*32;
    __shared__ float slab[32][DIM + 1];
    const int tid = threadIdx.x;
    for (int u = tid; u < 32*DIM; u += 256) {
        int rr = u >> 7, e = u & 127;
        float v = 0.f;
#pragma unroll
        for (int k = 0; k < KSPLIT; k++)
            v += g_P[(size_t)k*NN*DIM + (size_t)(base_r + rr)*DIM + e];
        g_Rf[(size_t)(base_r + rr)*DIM + e] = v;
        if (addS) g_S[(size_t)(base_r + rr)*DIM + e] += v;
        slab[rr][e] = v;
    }
    __syncthreads();
    int e = tid >> 1, hh = tid & 1;
    __nv_bfloat16* Rt = g_Rt[cur ^ 1];
#pragma unroll
    for (int k = 0; k < 16; k++) {
        int rr = hh*16 + k;
        float v = slab[rr][e];
        __nv_bfloat16 h = __float2bfloat16(v);
        __nv_bfloat16 l = __float2bfloat16(v - __bfloat162float(h));
        int col = base_r + rr;
        Rt[(size_t)e*KE + col]        = h;   // seg0: Rhi (pairs Thi)
        Rt[(size_t)e*KE + 2048 + col] = l;   // seg1: Rlo (pairs Thi)
        Rt[(size_t)e*KE + 4096 + col] = h;   // seg2: Rhi (pairs Tlo)
    }
}

// ---------------- combine kernels ----------------
__global__ void k_h(const float* __restrict__ bpre) {
    int e = blockIdx.x, tid = threadIdx.x;
    float s = 0.f;
    for (int r = tid; r < NN; r += 256) s += g_beta[r] * g_S[(size_t)r*DIM + e];
    if (tid < DIM) s += bpre[tid] * g_Rf[(size_t)tid*DIM + e];
    __shared__ float red[256];
    red[tid] = s;
    __syncthreads();
    for (int off = 128; off > 0; off >>= 1) {
        if (tid < off) red[tid] += red[tid + off];
        __syncthreads();
    }
    if (tid == 0) g_h[e] = red[0];
}

__global__ void k_T1() {
    int d = blockIdx.y;
    int q = blockIdx.x*128 + threadIdx.x;
    const float* __restrict__ Er = g_Rf + (size_t)d*DIM;
    float acc = 0.f;
#pragma unroll 8
    for (int e = 0; e < DIM; e++) acc += Er[e] * g_WpostT[e*OUTC + q];
    g_T1[d*OUTC + q] = acc;
}

__global__ void k_G(const float* __restrict__ Wpre) {
    int p = blockIdx.y;
    int q = blockIdx.x*128 + threadIdx.x;
    float acc = 0.f;
#pragma unroll 8
    for (int d = 0; d < DIM; d++) acc += Wpre[d*INC + p] * g_T1[d*OUTC + q];
    g_G[p*OUTC + q] = acc;
}

__global__ void k_dvec(const float* __restrict__ bpost) {
    int q = blockIdx.x*128 + threadIdx.x;
    float acc = bpost[q];
#pragma unroll 8
    for (int e = 0; e < DIM; e++) acc += g_h[e] * g_WpostT[e*OUTC + q];
    g_dvec[q] = acc;
}

// inp -> [Ihi|Ihi|Ilo]
__global__ void k_split_inp(const float* __restrict__ inp) {
    int b = blockIdx.x;
    for (int q = threadIdx.x; q < INC; q += 128) {
        float x = inp[(size_t)b*INC + q];
        __nv_bfloat16 h = __float2bfloat16(x);
        __nv_bfloat16 l = __float2bfloat16(x - __bfloat162float(h));
        size_t ro = (size_t)b*KEF;
        g_Iext[ro + q]        = h;
        g_Iext[ro + 512 + q]  = h;
        g_Iext[ro + 1024 + q] = l;
    }
}
// Gext row q over p: [hi(G[p][q]) | lo(G[p][q]) | hi(G[p][q])]  (FIX: was transposed)
__global__ void k_split_G() {
    int q = blockIdx.x;
    for (int p = threadIdx.x; p < INC; p += 128) {
        float x = g_G[(size_t)p*OUTC + q];
        __nv_bfloat16 h = __float2bfloat16(x);
        __nv_bfloat16 l = __float2bfloat16(x - __bfloat162float(h));
        size_t ro = (size_t)q*KEF;
        g_Gext[ro + p]        = h;
        g_Gext[ro + 512 + p]  = l;
        g_Gext[ro + 1024 + p] = h;
    }
}

// ---------------- launch ----------------
extern "C" void kernel_launch(void* const* d_in, const int* in_sizes, int n_in,
                              void* d_out, int out_size) {
    (void)in_sizes; (void)n_in; (void)out_size;
    const float* inp   = (const float*)d_in[0];
    const float* Wpre  = (const float*)d_in[1];
    const float* bpre  = (const float*)d_in[2];
    const float* W     = (const float*)d_in[3];
    const float* bl    = (const float*)d_in[4];
    const float* life  = (const float*)d_in[5];
    const float* Wpost = (const float*)d_in[6];
    const float* bpost = (const float*)d_in[7];
    float* out = (float*)d_out;

    k_prep<<<NUM, DIM>>>(life, bl);
    k_transpose<<<DIM, OUTC>>>(Wpost);
    k_make_T<<<dim3(NUM, NUM), 256>>>(W, life);
    k_init0<<<DIM, 256>>>();
    k_initS<<<NN, DIM>>>();
    k_split_inp<<<BATCH, 128>>>(inp);

    int cur = 0;
    for (int s = 0; s < STEPS; s++) {
        k_mma_step<<<dim3(KSPLIT, NUM), 256>>>(cur);
        k_reduce2<<<dim3(NUM, 4), 256>>>(cur, (s < STEPS - 1) ? 1 : 0);
        cur ^= 1;
    }

    k_h<<<DIM, 256>>>(bpre);
    k_T1<<<dim3(OUTC/128, DIM), 128>>>();
    k_G<<<dim3(OUTC/128, INC), 128>>>(Wpre);
    k_dvec<<<OUTC/128, 128>>>(bpost);
    k_split_G<<<OUTC, 128>>>();
    k_mma_fin<<<dim3(OUTC/128, BATCH/128), 256>>>(out);
    k_bias<<<BATCH*OUTC/1024, 256>>>(out);
}